// round 3
// baseline (speedup 1.0000x reference)
#include <cuda_runtime.h>
#include <cstdint>

// MaxPoolAggregator: out[q, :] = max_{s<10} features[nbrs[q,s], :]
// features: [1'000'000, 128] f32, nbrs: [100'000, 10] i32, out: [100'000, 128] f32
//
// One warp per query. Each lane owns one float4 (4 consecutive feature dims):
// 32 lanes * 4 = 128 dims. All 10 gathered rows are loaded with independent
// LDG.E.128 (high MLP), then reduced with fmaxf.

#define NUM_SAMPLE 10
#define D_FEAT 128
#define D_VEC (D_FEAT / 4)   // 32 float4 per row == one per lane

__global__ __launch_bounds__(256) void maxpool_agg_kernel(
    const float4* __restrict__ features,   // [N_NODES, 32] as float4
    const int* __restrict__ nbrs,          // [Q, 10]
    float4* __restrict__ out,              // [Q, 32] as float4
    int num_query)
{
    const int warp_global = (blockIdx.x * blockDim.x + threadIdx.x) >> 5;
    const int lane = threadIdx.x & 31;
    if (warp_global >= num_query) return;

    // Broadcast-load the 10 neighbor ids (all lanes read same addresses ->
    // single sector each, L1-broadcast, negligible cost vs. the 512B gathers).
    const int* nb = nbrs + (size_t)warp_global * NUM_SAMPLE;
    int ids[NUM_SAMPLE];
#pragma unroll
    for (int s = 0; s < NUM_SAMPLE; ++s) ids[s] = nb[s];

    // Issue all 10 gathers up front for maximal MLP.
    float4 v[NUM_SAMPLE];
#pragma unroll
    for (int s = 0; s < NUM_SAMPLE; ++s) {
        v[s] = features[(size_t)ids[s] * D_VEC + lane];
    }

    float4 m = v[0];
#pragma unroll
    for (int s = 1; s < NUM_SAMPLE; ++s) {
        m.x = fmaxf(m.x, v[s].x);
        m.y = fmaxf(m.y, v[s].y);
        m.z = fmaxf(m.z, v[s].z);
        m.w = fmaxf(m.w, v[s].w);
    }

    out[(size_t)warp_global * D_VEC + lane] = m;
}

extern "C" void kernel_launch(void* const* d_in, const int* in_sizes, int n_in,
                              void* d_out, int out_size)
{
    const float4* features = (const float4*)d_in[0];
    const int*    nbrs     = (const int*)d_in[1];
    // d_in[2] is num_sample (device scalar) — shape is static, hardcoded to 10.

    const int num_query = in_sizes[1] / NUM_SAMPLE;   // 100'000

    const int warps_per_block = 8;                    // 256 threads
    const int threads = warps_per_block * 32;
    const int blocks = (num_query + warps_per_block - 1) / warps_per_block;

    maxpool_agg_kernel<<<blocks, threads>>>(features, nbrs, (float4*)d_out, num_query);
}

// round 5
// speedup vs baseline: 1.0083x; 1.0083x over previous
#include <cuda_runtime.h>
#include <cstdint>

// MaxPoolAggregator: out[q, :] = max_{s<10} features[nbrs[q,s], :]
// features: [1'000'000, 128] f32, nbrs: [100'000, 10] i32, out: [100'000, 128] f32
//
// One warp per query, one float4 per lane (perfectly coalesced 512B row reads).
// R4: evict-last on feature gathers via createpolicy + L2::cache_hint
//     (inline .L2::evict_last is only legal on 256-bit ld on sm_103a),
//     streaming (evict-first) stores for the write-once output,
//     128-thread CTAs for occupancy.

#define NUM_SAMPLE 10
#define D_FEAT 128
#define D_VEC (D_FEAT / 4)   // 32 float4 per row == one per lane

__device__ __forceinline__ uint64_t make_evict_last_policy() {
    uint64_t policy;
    asm("createpolicy.fractional.L2::evict_last.b64 %0, 1.0;" : "=l"(policy));
    return policy;
}

__device__ __forceinline__ float4 ldg_evict_last(const float4* p, uint64_t policy) {
    float4 v;
    asm volatile("ld.global.nc.L2::cache_hint.v4.f32 {%0,%1,%2,%3}, [%4], %5;"
                 : "=f"(v.x), "=f"(v.y), "=f"(v.z), "=f"(v.w)
                 : "l"(p), "l"(policy));
    return v;
}

__device__ __forceinline__ void stg_streaming(float4* p, float4 v) {
    asm volatile("st.global.cs.v4.f32 [%0], {%1,%2,%3,%4};"
                 :: "l"(p), "f"(v.x), "f"(v.y), "f"(v.z), "f"(v.w)
                 : "memory");
}

__global__ __launch_bounds__(128) void maxpool_agg_kernel(
    const float4* __restrict__ features,   // [N_NODES, 32] as float4
    const int* __restrict__ nbrs,          // [Q, 10]
    float4* __restrict__ out,              // [Q, 32] as float4
    int num_query)
{
    const int warp_global = (blockIdx.x * blockDim.x + threadIdx.x) >> 5;
    const int lane = threadIdx.x & 31;
    if (warp_global >= num_query) return;

    const uint64_t policy = make_evict_last_policy();

    // Broadcast-load the 10 neighbor ids (uniform per warp, L1-broadcast).
    const int* nb = nbrs + (size_t)warp_global * NUM_SAMPLE;
    int ids[NUM_SAMPLE];
#pragma unroll
    for (int s = 0; s < NUM_SAMPLE; ++s) ids[s] = __ldg(nb + s);

    // Issue all 10 gathers up front for maximal MLP; evict_last keeps the
    // fetched rows resident in L2 so duplicate samples (~37% of all samples)
    // can hit L2 instead of re-touching DRAM.
    float4 v[NUM_SAMPLE];
#pragma unroll
    for (int s = 0; s < NUM_SAMPLE; ++s) {
        v[s] = ldg_evict_last(features + (size_t)ids[s] * D_VEC + lane, policy);
    }

    float4 m = v[0];
#pragma unroll
    for (int s = 1; s < NUM_SAMPLE; ++s) {
        m.x = fmaxf(m.x, v[s].x);
        m.y = fmaxf(m.y, v[s].y);
        m.z = fmaxf(m.z, v[s].z);
        m.w = fmaxf(m.w, v[s].w);
    }

    // Output is write-once dead data: streaming store, evict-first in L2.
    stg_streaming(out + (size_t)warp_global * D_VEC + lane, m);
}

extern "C" void kernel_launch(void* const* d_in, const int* in_sizes, int n_in,
                              void* d_out, int out_size)
{
    const float4* features = (const float4*)d_in[0];
    const int*    nbrs     = (const int*)d_in[1];
    // d_in[2] is num_sample (device scalar) — shape is static, hardcoded to 10.

    const int num_query = in_sizes[1] / NUM_SAMPLE;   // 100'000

    const int warps_per_block = 4;                    // 128 threads
    const int threads = warps_per_block * 32;
    const int blocks = (num_query + warps_per_block - 1) / warps_per_block;

    maxpool_agg_kernel<<<blocks, threads>>>(features, nbrs, (float4*)d_out, num_query);
}